// round 15
// baseline (speedup 1.0000x reference)
#include <cuda_runtime.h>
#include <cuda_fp16.h>
#include <math.h>
#include <stdint.h>

// Problem constants
#define B_ 2
#define L_ 2048
#define D_ 1024
#define H_ 16
#define HD_ 64
#define M_ROWS (B_ * L_)   // 4096
#define GK 1024
#define GN 1024

// Scratch (allocation-free rule: __device__ globals) — all half
__device__ __half g_q[M_ROWS * D_];
__device__ __half g_k[M_ROWS * D_];
__device__ __half g_v[M_ROWS * D_];
__device__ __half g_ctx[M_ROWS * D_];
__device__ __half g_x0[M_ROWS * D_];
__device__ __half g_x1[M_ROWS * D_];
__device__ __half g_x2[M_ROWS * D_];
__device__ __half g_w0[D_ * D_];
__device__ __half g_w1[D_ * D_];
__device__ __half g_w2[D_ * D_];
__device__ __half g_w3[D_ * D_];
__device__ unsigned g_mpack[B_ * L_ * (L_ / 32)];

// ===========================================================================
// Helpers
// ===========================================================================
__device__ __forceinline__ uint32_t smem_u32(const void* p) {
    uint32_t a;
    asm("{ .reg .u64 t; cvta.to.shared.u64 t, %1; cvt.u32.u64 %0, t; }" : "=r"(a) : "l"(p));
    return a;
}
#define CP_ASYNC16(s, g) \
    asm volatile("cp.async.cg.shared.global [%0], [%1], 16;" :: "r"(s), "l"(g))
#define CP_ASYNC8(s, g) \
    asm volatile("cp.async.ca.shared.global [%0], [%1], 8;" :: "r"(s), "l"(g))
#define CP_COMMIT() asm volatile("cp.async.commit_group;" ::: "memory")
#define CP_WAIT0()  asm volatile("cp.async.wait_group 0;" ::: "memory")
#define CP_WAIT1()  asm volatile("cp.async.wait_group 1;" ::: "memory")

// pack two f32 -> f16x2 (round-to-nearest)
__device__ __forceinline__ uint32_t f16x2(float lo, float hi) {
    uint32_t r;
    asm("cvt.rn.f16x2.f32 %0, %1, %2;" : "=r"(r) : "f"(hi), "f"(lo));
    return r;
}

// mma.sync fp16: D(16x8) += A(16x16) * B(16x8), fp32 accum
__device__ __forceinline__ void mma_f16(float* d, const uint32_t* a, const uint32_t* b) {
    asm volatile(
        "mma.sync.aligned.m16n8k16.row.col.f32.f16.f16.f32 "
        "{%0,%1,%2,%3}, {%4,%5,%6,%7}, {%8,%9}, {%0,%1,%2,%3};"
        : "+f"(d[0]), "+f"(d[1]), "+f"(d[2]), "+f"(d[3])
        : "r"(a[0]), "r"(a[1]), "r"(a[2]), "r"(a[3]), "r"(b[0]), "r"(b[1]));
}

__device__ __forceinline__ void ldsm_x4(uint32_t* r, uint32_t addr) {
    asm volatile("ldmatrix.sync.aligned.m8n8.x4.shared.b16 {%0,%1,%2,%3}, [%4];"
        : "=r"(r[0]), "=r"(r[1]), "=r"(r[2]), "=r"(r[3]) : "r"(addr));
}
__device__ __forceinline__ void ldsm_x4_t(uint32_t* r, uint32_t addr) {
    asm volatile("ldmatrix.sync.aligned.m8n8.x4.trans.shared.b16 {%0,%1,%2,%3}, [%4];"
        : "=r"(r[0]), "=r"(r[1]), "=r"(r[2]), "=r"(r[3]) : "r"(addr));
}

// ===========================================================================
// fp32 -> fp16 rounding pass (8 floats / thread)
// ===========================================================================
__global__ __launch_bounds__(256) void round_half_many(
    const float* __restrict__ i0, const float* __restrict__ i1,
    const float* __restrict__ i2, const float* __restrict__ i3,
    __half* __restrict__ o0, __half* __restrict__ o1,
    __half* __restrict__ o2, __half* __restrict__ o3)
{
    const int z = blockIdx.y;
    const float* in = (z == 0) ? i0 : (z == 1) ? i1 : (z == 2) ? i2 : i3;
    __half* out = (z == 0) ? o0 : (z == 1) ? o1 : (z == 2) ? o2 : o3;
    int idx = blockIdx.x * 256 + threadIdx.x;
    float4 a = ((const float4*)in)[idx * 2];
    float4 b = ((const float4*)in)[idx * 2 + 1];
    uint4 o;
    o.x = f16x2(a.x, a.y);
    o.y = f16x2(a.z, a.w);
    o.z = f16x2(b.x, b.y);
    o.w = f16x2(b.z, b.w);
    ((uint4*)out)[idx] = o;
}

// ===========================================================================
// Mask bit-pack: each warp packs 128 ints via 4 ballots; block = 1024 ints
// ===========================================================================
__global__ __launch_bounds__(256) void mask_pack_kernel(
    const int* __restrict__ m, unsigned* __restrict__ out)
{
    int warp = blockIdx.x * 8 + (threadIdx.x >> 5);
    int lane = threadIdx.x & 31;
    size_t base = (size_t)warp * 128;
    int v0 = m[base + lane], v1 = m[base + 32 + lane];
    int v2 = m[base + 64 + lane], v3 = m[base + 96 + lane];
    unsigned w0 = __ballot_sync(0xFFFFFFFFu, v0 != 0);
    unsigned w1 = __ballot_sync(0xFFFFFFFFu, v1 != 0);
    unsigned w2 = __ballot_sync(0xFFFFFFFFu, v2 != 0);
    unsigned w3 = __ballot_sync(0xFFFFFFFFu, v3 != 0);
    if (lane == 0) {
        out[warp * 4 + 0] = w0; out[warp * 4 + 1] = w1;
        out[warp * 4 + 2] = w2; out[warp * 4 + 3] = w3;
    }
}

// ===========================================================================
// fp16 mma.sync NT GEMM (unchanged from R14; 2 CTAs/SM, reg cap 128)
// ===========================================================================
#define RB 144                           // bytes per smem row (64 halves + pad)
#define ATILE_B (128 * RB)               // 18432
#define STAGE_B (2 * ATILE_B)            // 36864
#define GEMM_SMEM (3 * STAGE_B)          // 110592

__global__ __launch_bounds__(256, 2) void gemm_tc(
    const __half* __restrict__ A0, const __half* __restrict__ A1, const __half* __restrict__ A2,
    const __half* __restrict__ B0, const __half* __restrict__ B1, const __half* __restrict__ B2,
    void* __restrict__ C0, void* __restrict__ C1, void* __restrict__ C2,
    int half_out)
{
    extern __shared__ char smem[];
    uint32_t sb = smem_u32(smem);
    const int tid  = threadIdx.x;
    const int lane = tid & 31;
    const int wid  = tid >> 5;
    const int warp_m = wid & 1;
    const int warp_n = wid >> 1;
    const int bm = blockIdx.y * 128;
    const int bn = blockIdx.x * 128;
    const int z  = blockIdx.z;

    const __half* A = (z == 0) ? A0 : (z == 1) ? A1 : A2;
    const __half* Bw = (z == 0) ? B0 : (z == 1) ? B1 : B2;
    void* C = (z == 0) ? C0 : (z == 1) ? C1 : C2;

    const char* Ab = (const char*)(A + (size_t)bm * GK);
    const char* Bb = (const char*)(Bw + (size_t)bn * GK);

#define ISSUE(kc, st) do {                                                    \
        uint32_t sA = sb + (uint32_t)(st) * STAGE_B;                          \
        uint32_t sB = sA + ATILE_B;                                           \
        size_t koff = (size_t)(kc) * 128;                                     \
        _Pragma("unroll")                                                     \
        for (int _i = 0; _i < 4; _i++) {                                      \
            int idx = tid + _i * 256;                                         \
            int r  = idx >> 3;                                                \
            int ch = (idx & 7) << 4;                                          \
            CP_ASYNC16(sA + r * RB + ch, Ab + (size_t)r * 2048 + koff + ch);  \
            CP_ASYNC16(sB + r * RB + ch, Bb + (size_t)r * 2048 + koff + ch);  \
        }                                                                     \
    } while (0)

    float acc[4][4][4];
#pragma unroll
    for (int mt = 0; mt < 4; mt++)
#pragma unroll
        for (int nt = 0; nt < 4; nt++)
#pragma unroll
            for (int r = 0; r < 4; r++) acc[mt][nt][r] = 0.0f;

    ISSUE(0, 0); CP_COMMIT();
    ISSUE(1, 1); CP_COMMIT();

    const int mL = lane >> 3, rL = lane & 7;
    const uint32_t offA = (uint32_t)(warp_m * 64 + (mL & 1) * 8 + rL) * RB + (mL >> 1) * 16;
    const uint32_t offB = (uint32_t)(warp_n * 32 + ((mL >= 2) ? 8 : 0) + rL) * RB + (mL & 1) * 16;

    const int lq = lane >> 2;
    const int lr = lane & 3;

    for (int kc = 0; kc < 16; kc++) {
        CP_WAIT1();
        __syncthreads();
        if (kc + 2 < 16) { ISSUE(kc + 2, (kc + 2) % 3); CP_COMMIT(); }

        const uint32_t stA = sb + (uint32_t)(kc % 3) * STAGE_B;
        const uint32_t stB = stA + ATILE_B;

#pragma unroll
        for (int ks = 0; ks < 4; ks++) {
            uint32_t af[4][4];
#pragma unroll
            for (int mt = 0; mt < 4; mt++)
                ldsm_x4(af[mt], stA + offA + mt * (16 * RB) + ks * 32);
            uint32_t b4[2][4];
#pragma unroll
            for (int ntp = 0; ntp < 2; ntp++)
                ldsm_x4(b4[ntp], stB + offB + ntp * (16 * RB) + ks * 32);
#pragma unroll
            for (int mt = 0; mt < 4; mt++)
#pragma unroll
                for (int nt = 0; nt < 4; nt++)
                    mma_f16(acc[mt][nt], af[mt], &b4[nt >> 1][(nt & 1) * 2]);
        }
    }

#pragma unroll
    for (int mt = 0; mt < 4; mt++) {
        int row = bm + warp_m * 64 + mt * 16 + lq;
#pragma unroll
        for (int nt = 0; nt < 4; nt++) {
            int col = bn + warp_n * 32 + nt * 8 + lr * 2;
            if (half_out) {
                uint32_t* Ch = (uint32_t*)C;
                Ch[((size_t)row * GN + col) >> 1]       = f16x2(acc[mt][nt][0], acc[mt][nt][1]);
                Ch[((size_t)(row + 8) * GN + col) >> 1] = f16x2(acc[mt][nt][2], acc[mt][nt][3]);
            } else {
                float* Cf = (float*)C;
                *(float2*)&Cf[(size_t)row * GN + col]       = make_float2(acc[mt][nt][0], acc[mt][nt][1]);
                *(float2*)&Cf[(size_t)(row + 8) * GN + col] = make_float2(acc[mt][nt][2], acc[mt][nt][3]);
            }
        }
    }
#undef ISSUE
}

// ===========================================================================
// Flash attention fp16 v5: 64 q-rows/CTA, 4 warps x 16 rows.
// P lives in a PER-WARP PRIVATE smem region -> NO mid-tile barrier.
// One syncthreads per tile (stage protection only). 4 CTAs/SM.
// ===========================================================================
#define AST_KS 0
#define AST_VS (64 * RB)                          // 9216
#define AST_MW (2 * 64 * RB)                      // 18432
#define AST_BYTES (AST_MW + 1024)                 // 19456
#define PPRIV (2 * AST_BYTES)                     // 38912: per-warp P (4x16 rows)
#define ATTN_SMEM (PPRIV + 64 * RB)               // 48128
#define LW (L_ / 32)

__global__ __launch_bounds__(128, 4) void attn_tc(
    const __half* __restrict__ Q, const __half* __restrict__ Kg,
    const __half* __restrict__ V, const unsigned* __restrict__ mp,
    __half* __restrict__ ctx)
{
    extern __shared__ char smem[];
    uint32_t sb = smem_u32(smem);

    const int tid  = threadIdx.x;
    const int lane = tid & 31;
    const int wid  = tid >> 5;
    const int lq = lane >> 2;
    const int lr = lane & 3;
    const int bh = blockIdx.y;
    const int b  = bh >> 4;
    const int h  = bh & 15;
    const int q0 = blockIdx.x * 64;

    const size_t head_off = (size_t)h * HD_;

    const int mL = lane >> 3, rL = lane & 7;
    // A-side frags from the warp's private region (rows 0..15 within region)
    const uint32_t offP = PPRIV + (uint32_t)wid * (16 * RB)
                        + (uint32_t)((mL & 1) * 8 + rL) * RB + (mL >> 1) * 16;
    const uint32_t offK = (uint32_t)(((mL >= 2) ? 8 : 0) + rL) * RB + (mL & 1) * 16;
    const uint32_t offV = (uint32_t)rL * RB + (uint32_t)mL * 16;

    const int ra = wid * 16 + lq;
    const int rb = ra + 8;

#define AISSUE(t, st) do {                                                     \
        uint32_t base = sb + (uint32_t)(st) * AST_BYTES;                       \
        int k0_ = (t) * 64;                                                    \
        _Pragma("unroll")                                                      \
        for (int _i = 0; _i < 4; _i++) {                                       \
            int idx = tid + _i * 128;                                          \
            int r  = idx >> 3;                                                 \
            int ch = (idx & 7) << 4;                                           \
            const char* gk = (const char*)Kg + ((size_t)(b * L_ + k0_ + r) * D_ + head_off) * 2 + ch; \
            const char* gv = (const char*)V  + ((size_t)(b * L_ + k0_ + r) * D_ + head_off) * 2 + ch; \
            CP_ASYNC16(base + AST_KS + r * RB + ch, gk);                       \
            CP_ASYNC16(base + AST_VS + r * RB + ch, gv);                       \
        }                                                                      \
        if (tid < 64) {                                                        \
            const char* gm = (const char*)(mp + (size_t)(b * L_ + q0 + tid) * LW + ((t) << 1)); \
            CP_ASYNC8(base + AST_MW + tid * 8, gm);                            \
        }                                                                      \
    } while (0)

    // ---- stage Q into the private-P region (linear layout matches) ----
    {
        uint32_t qdst = sb + PPRIV;
#pragma unroll
        for (int _i = 0; _i < 4; _i++) {
            int idx = tid + _i * 128;
            int r  = idx >> 3;
            int ch = (idx & 7) << 4;
            const char* gq = (const char*)Q + ((size_t)(b * L_ + q0 + r) * D_ + head_off) * 2 + ch;
            CP_ASYNC16(qdst + r * RB + ch, gq);
        }
    }
    AISSUE(0, 0);
    CP_COMMIT();
    CP_WAIT0();
    __syncthreads();

    uint32_t qa[4][4];
#pragma unroll
    for (int s = 0; s < 4; s++)
        ldsm_x4(qa[s], sb + offP + s * 32);
    // no barrier needed: each warp's P region is written only by itself later

    float oacc[8][4];
#pragma unroll
    for (int nt = 0; nt < 8; nt++)
#pragma unroll
        for (int e = 0; e < 4; e++) oacc[nt][e] = 0.0f;

    float l0 = 0.0f, l1 = 0.0f;

    for (int t = 0; t < 32; t++) {
        if (t > 0) { CP_WAIT0(); __syncthreads(); }
        if (t + 1 < 32) { AISSUE(t + 1, (t + 1) & 1); CP_COMMIT(); }

        const uint32_t stg  = sb + (uint32_t)(t & 1) * AST_BYTES;
        const uint32_t stgV = stg + AST_VS;
        const unsigned* Mw = (const unsigned*)(smem + (t & 1) * AST_BYTES + AST_MW);

        // ---- S = Q K^T ----
        float sacc[8][4];
#pragma unroll
        for (int nt = 0; nt < 8; nt++)
#pragma unroll
            for (int e = 0; e < 4; e++) sacc[nt][e] = 0.0f;

#pragma unroll
        for (int s = 0; s < 4; s++) {
            uint32_t kb4[4][4];
#pragma unroll
            for (int ntp = 0; ntp < 4; ntp++)
                ldsm_x4(kb4[ntp], stg + offK + ntp * (16 * RB) + s * 32);
#pragma unroll
            for (int nt = 0; nt < 8; nt++)
                mma_f16(sacc[nt], qa[s], &kb4[nt >> 1][(nt & 1) * 2]);
        }

        // ---- exp + mask + store P into this warp's PRIVATE region ----
        const unsigned w0a = Mw[ra * 2], w0b = Mw[ra * 2 + 1];
        const unsigned w1a = Mw[rb * 2], w1b = Mw[rb * 2 + 1];
        char* Pc = (char*)smem + PPRIV + wid * (16 * RB);
#pragma unroll
        for (int nt = 0; nt < 8; nt++) {
            const int c = nt * 8 + 2 * lr;
            const int sh = c & 31;
            const unsigned wA = (nt < 4) ? w0a : w0b;
            const unsigned wB = (nt < 4) ? w1a : w1b;
            float p0 = ((wA >> sh) & 1u)       ? 0.0f : __expf(sacc[nt][0] * 0.125f);
            float p1 = ((wA >> (sh + 1)) & 1u) ? 0.0f : __expf(sacc[nt][1] * 0.125f);
            float p2 = ((wB >> sh) & 1u)       ? 0.0f : __expf(sacc[nt][2] * 0.125f);
            float p3 = ((wB >> (sh + 1)) & 1u) ? 0.0f : __expf(sacc[nt][3] * 0.125f);
            l0 += p0 + p1;
            l1 += p2 + p3;
            *(uint32_t*)(Pc + lq * RB + c * 2)       = f16x2(p0, p1);
            *(uint32_t*)(Pc + (lq + 8) * RB + c * 2) = f16x2(p2, p3);
        }
        __syncwarp();      // intra-warp: ldmatrix reads other lanes' stores

        // ---- O += P V : V via trans-ldsm ----
#pragma unroll
        for (int s = 0; s < 4; s++) {
            uint32_t vA[4], vB[4], vC[4], vD[4];
            ldsm_x4_t(vA, stgV + offV + (s * 16 + 0) * RB + 0);
            ldsm_x4_t(vB, stgV + offV + (s * 16 + 8) * RB + 0);
            ldsm_x4_t(vC, stgV + offV + (s * 16 + 0) * RB + 64);
            ldsm_x4_t(vD, stgV + offV + (s * 16 + 8) * RB + 64);
            uint32_t pa[4];
            ldsm_x4(pa, sb + offP + s * 32);
            uint32_t vb[8][2];
#pragma unroll
            for (int o = 0; o < 4; o++) {
                vb[o][0] = vA[o];     vb[o][1] = vB[o];
                vb[o + 4][0] = vC[o]; vb[o + 4][1] = vD[o];
            }
#pragma unroll
            for (int nt = 0; nt < 8; nt++)
                mma_f16(oacc[nt], pa, vb[nt]);
        }
        __syncwarp();      // P reads done before next tile's P stores (intra-warp)
    }

    // ---- epilogue: quad-reduce denominators, normalize, store half ----
    l0 += __shfl_xor_sync(0xFFFFFFFFu, l0, 1);
    l0 += __shfl_xor_sync(0xFFFFFFFFu, l0, 2);
    l1 += __shfl_xor_sync(0xFFFFFFFFu, l1, 1);
    l1 += __shfl_xor_sync(0xFFFFFFFFu, l1, 2);
    float inv0 = 1.0f / l0, inv1 = 1.0f / l1;
    uint32_t* ctxu = (uint32_t*)ctx;
#pragma unroll
    for (int nt = 0; nt < 8; nt++) {
        int col = nt * 8 + 2 * lr;
        ctxu[(((size_t)(b * L_ + q0 + ra)) * D_ + head_off + col) >> 1] =
            f16x2(oacc[nt][0] * inv0, oacc[nt][1] * inv0);
        ctxu[(((size_t)(b * L_ + q0 + rb)) * D_ + head_off + col) >> 1] =
            f16x2(oacc[nt][2] * inv1, oacc[nt][3] * inv1);
    }
#undef AISSUE
}

// ---------------------------------------------------------------------------
extern "C" void kernel_launch(void* const* d_in, const int* in_sizes, int n_in,
                              void* d_out, int out_size)
{
    const float* q_in = (const float*)d_in[0];
    const float* k_in = (const float*)d_in[1];
    const float* v_in = (const float*)d_in[2];
    const float* Wq   = (const float*)d_in[3];
    const float* Wk   = (const float*)d_in[4];
    const float* Wv   = (const float*)d_in[5];
    const float* Wo   = (const float*)d_in[6];
    const int*   mask = (const int*)d_in[7];
    float* out = (float*)d_out;

    __half *pq, *pk, *pv, *pctx, *px0, *px1, *px2, *pw0, *pw1, *pw2, *pw3;
    unsigned* pm;
    cudaGetSymbolAddress((void**)&pq,   g_q);
    cudaGetSymbolAddress((void**)&pk,   g_k);
    cudaGetSymbolAddress((void**)&pv,   g_v);
    cudaGetSymbolAddress((void**)&pctx, g_ctx);
    cudaGetSymbolAddress((void**)&px0,  g_x0);
    cudaGetSymbolAddress((void**)&px1,  g_x1);
    cudaGetSymbolAddress((void**)&px2,  g_x2);
    cudaGetSymbolAddress((void**)&pw0,  g_w0);
    cudaGetSymbolAddress((void**)&pw1,  g_w1);
    cudaGetSymbolAddress((void**)&pw2,  g_w2);
    cudaGetSymbolAddress((void**)&pw3,  g_w3);
    cudaGetSymbolAddress((void**)&pm,   g_mpack);

    cudaFuncSetAttribute(gemm_tc, cudaFuncAttributeMaxDynamicSharedMemorySize, GEMM_SMEM);
    cudaFuncSetAttribute(attn_tc, cudaFuncAttributeMaxDynamicSharedMemorySize, ATTN_SMEM);

    // 8 warps/block x 128 ints/warp = 1024 ints per block
    mask_pack_kernel<<<(B_ * L_ * L_) / 1024, 256>>>(mask, pm);

    // fp32 -> fp16 rounding: inputs (z=3), weights (z=4); 8 floats/thread
    round_half_many<<<dim3(M_ROWS * D_ / 2048, 3), 256>>>(
        q_in, k_in, v_in, q_in, px0, px1, px2, px0);
    round_half_many<<<dim3(D_ * D_ / 2048, 4), 256>>>(
        Wq, Wk, Wv, Wo, pw0, pw1, pw2, pw3);

    // Fused QKV projections (grid.z = 3), fp16 outputs
    gemm_tc<<<dim3(GN / 128, M_ROWS / 128, 3), 256, GEMM_SMEM>>>(
        px0, px1, px2, pw0, pw1, pw2, pq, pk, pv, 1);

    // Attention (64 q-rows/CTA, 4 CTAs/SM, barrier-light)
    attn_tc<<<dim3(L_ / 64, B_ * H_), 128, ATTN_SMEM>>>(pq, pk, pv, pm, pctx);

    // Output projection: fp32 out
    gemm_tc<<<dim3(GN / 128, M_ROWS / 128, 1), 256, GEMM_SMEM>>>(
        pctx, pctx, pctx, pw3, pw3, pw3, out, out, out, 0);
}

// round 16
// speedup vs baseline: 1.0661x; 1.0661x over previous
#include <cuda_runtime.h>
#include <cuda_fp16.h>
#include <math.h>
#include <stdint.h>

// Problem constants
#define B_ 2
#define L_ 2048
#define D_ 1024
#define H_ 16
#define HD_ 64
#define M_ROWS (B_ * L_)   // 4096
#define GK 1024
#define GN 1024

// Scratch (allocation-free rule: __device__ globals) — all half
__device__ __half g_q[M_ROWS * D_];
__device__ __half g_k[M_ROWS * D_];
__device__ __half g_v[M_ROWS * D_];
__device__ __half g_ctx[M_ROWS * D_];
__device__ __half g_x0[M_ROWS * D_];
__device__ __half g_x1[M_ROWS * D_];
__device__ __half g_x2[M_ROWS * D_];
__device__ __half g_w0[D_ * D_];
__device__ __half g_w1[D_ * D_];
__device__ __half g_w2[D_ * D_];
__device__ __half g_w3[D_ * D_];
__device__ unsigned g_mpack[B_ * L_ * (L_ / 32)];

// ===========================================================================
// Helpers
// ===========================================================================
__device__ __forceinline__ uint32_t smem_u32(const void* p) {
    uint32_t a;
    asm("{ .reg .u64 t; cvta.to.shared.u64 t, %1; cvt.u32.u64 %0, t; }" : "=r"(a) : "l"(p));
    return a;
}
#define CP_ASYNC16(s, g) \
    asm volatile("cp.async.cg.shared.global [%0], [%1], 16;" :: "r"(s), "l"(g))
#define CP_ASYNC8(s, g) \
    asm volatile("cp.async.ca.shared.global [%0], [%1], 8;" :: "r"(s), "l"(g))
#define CP_COMMIT() asm volatile("cp.async.commit_group;" ::: "memory")
#define CP_WAIT0()  asm volatile("cp.async.wait_group 0;" ::: "memory")
#define CP_WAIT1()  asm volatile("cp.async.wait_group 1;" ::: "memory")

// pack two f32 -> f16x2 (round-to-nearest)
__device__ __forceinline__ uint32_t f16x2(float lo, float hi) {
    uint32_t r;
    asm("cvt.rn.f16x2.f32 %0, %1, %2;" : "=r"(r) : "f"(hi), "f"(lo));
    return r;
}

// mma.sync fp16: D(16x8) += A(16x16) * B(16x8), fp32 accum
__device__ __forceinline__ void mma_f16(float* d, const uint32_t* a, const uint32_t* b) {
    asm volatile(
        "mma.sync.aligned.m16n8k16.row.col.f32.f16.f16.f32 "
        "{%0,%1,%2,%3}, {%4,%5,%6,%7}, {%8,%9}, {%0,%1,%2,%3};"
        : "+f"(d[0]), "+f"(d[1]), "+f"(d[2]), "+f"(d[3])
        : "r"(a[0]), "r"(a[1]), "r"(a[2]), "r"(a[3]), "r"(b[0]), "r"(b[1]));
}

__device__ __forceinline__ void ldsm_x4(uint32_t* r, uint32_t addr) {
    asm volatile("ldmatrix.sync.aligned.m8n8.x4.shared.b16 {%0,%1,%2,%3}, [%4];"
        : "=r"(r[0]), "=r"(r[1]), "=r"(r[2]), "=r"(r[3]) : "r"(addr));
}
__device__ __forceinline__ void ldsm_x4_t(uint32_t* r, uint32_t addr) {
    asm volatile("ldmatrix.sync.aligned.m8n8.x4.trans.shared.b16 {%0,%1,%2,%3}, [%4];"
        : "=r"(r[0]), "=r"(r[1]), "=r"(r[2]), "=r"(r[3]) : "r"(addr));
}

// ===========================================================================
// fp32 -> fp16 rounding pass, ALL 7 arrays in one launch (grid.y = 7).
// z 0..2: activations (M_ROWS*D_), z 3..6: weights (D_*D_). Guard idles the
// surplus blocks for the smaller arrays.
// ===========================================================================
__global__ __launch_bounds__(256) void round_half_all(
    const float* __restrict__ i0, const float* __restrict__ i1,
    const float* __restrict__ i2, const float* __restrict__ i3,
    const float* __restrict__ i4, const float* __restrict__ i5,
    const float* __restrict__ i6,
    __half* __restrict__ o0, __half* __restrict__ o1,
    __half* __restrict__ o2, __half* __restrict__ o3,
    __half* __restrict__ o4, __half* __restrict__ o5,
    __half* __restrict__ o6)
{
    const int z = blockIdx.y;
    if (z >= 3 && blockIdx.x >= (D_ * D_) / 2048) return;
    const float* in;
    __half* out;
    switch (z) {
        case 0: in = i0; out = o0; break;
        case 1: in = i1; out = o1; break;
        case 2: in = i2; out = o2; break;
        case 3: in = i3; out = o3; break;
        case 4: in = i4; out = o4; break;
        case 5: in = i5; out = o5; break;
        default: in = i6; out = o6; break;
    }
    int idx = blockIdx.x * 256 + threadIdx.x;
    float4 a = ((const float4*)in)[idx * 2];
    float4 b = ((const float4*)in)[idx * 2 + 1];
    uint4 o;
    o.x = f16x2(a.x, a.y);
    o.y = f16x2(a.z, a.w);
    o.z = f16x2(b.x, b.y);
    o.w = f16x2(b.z, b.w);
    ((uint4*)out)[idx] = o;
}

// ===========================================================================
// Mask bit-pack: each warp packs 128 ints via 4 ballots; block = 1024 ints
// ===========================================================================
__global__ __launch_bounds__(256) void mask_pack_kernel(
    const int* __restrict__ m, unsigned* __restrict__ out)
{
    int warp = blockIdx.x * 8 + (threadIdx.x >> 5);
    int lane = threadIdx.x & 31;
    size_t base = (size_t)warp * 128;
    int v0 = m[base + lane], v1 = m[base + 32 + lane];
    int v2 = m[base + 64 + lane], v3 = m[base + 96 + lane];
    unsigned w0 = __ballot_sync(0xFFFFFFFFu, v0 != 0);
    unsigned w1 = __ballot_sync(0xFFFFFFFFu, v1 != 0);
    unsigned w2 = __ballot_sync(0xFFFFFFFFu, v2 != 0);
    unsigned w3 = __ballot_sync(0xFFFFFFFFu, v3 != 0);
    if (lane == 0) {
        out[warp * 4 + 0] = w0; out[warp * 4 + 1] = w1;
        out[warp * 4 + 2] = w2; out[warp * 4 + 3] = w3;
    }
}

// ===========================================================================
// fp16 mma.sync NT GEMM (2 CTAs/SM, reg cap 128).
// qscale applied to z==0 half-output (folds attention 1/sqrt(HD) into Q).
// ===========================================================================
#define RB 144                           // bytes per smem row (64 halves + pad)
#define ATILE_B (128 * RB)               // 18432
#define STAGE_B (2 * ATILE_B)            // 36864
#define GEMM_SMEM (3 * STAGE_B)          // 110592

__global__ __launch_bounds__(256, 2) void gemm_tc(
    const __half* __restrict__ A0, const __half* __restrict__ A1, const __half* __restrict__ A2,
    const __half* __restrict__ B0, const __half* __restrict__ B1, const __half* __restrict__ B2,
    void* __restrict__ C0, void* __restrict__ C1, void* __restrict__ C2,
    int half_out, float qscale)
{
    extern __shared__ char smem[];
    uint32_t sb = smem_u32(smem);
    const int tid  = threadIdx.x;
    const int lane = tid & 31;
    const int wid  = tid >> 5;
    const int warp_m = wid & 1;
    const int warp_n = wid >> 1;
    const int bm = blockIdx.y * 128;
    const int bn = blockIdx.x * 128;
    const int z  = blockIdx.z;

    const __half* A = (z == 0) ? A0 : (z == 1) ? A1 : A2;
    const __half* Bw = (z == 0) ? B0 : (z == 1) ? B1 : B2;
    void* C = (z == 0) ? C0 : (z == 1) ? C1 : C2;
    const float sc = (half_out && z == 0) ? qscale : 1.0f;

    const char* Ab = (const char*)(A + (size_t)bm * GK);
    const char* Bb = (const char*)(Bw + (size_t)bn * GK);

#define ISSUE(kc, st) do {                                                    \
        uint32_t sA = sb + (uint32_t)(st) * STAGE_B;                          \
        uint32_t sB = sA + ATILE_B;                                           \
        size_t koff = (size_t)(kc) * 128;                                     \
        _Pragma("unroll")                                                     \
        for (int _i = 0; _i < 4; _i++) {                                      \
            int idx = tid + _i * 256;                                         \
            int r  = idx >> 3;                                                \
            int ch = (idx & 7) << 4;                                          \
            CP_ASYNC16(sA + r * RB + ch, Ab + (size_t)r * 2048 + koff + ch);  \
            CP_ASYNC16(sB + r * RB + ch, Bb + (size_t)r * 2048 + koff + ch);  \
        }                                                                     \
    } while (0)

    float acc[4][4][4];
#pragma unroll
    for (int mt = 0; mt < 4; mt++)
#pragma unroll
        for (int nt = 0; nt < 4; nt++)
#pragma unroll
            for (int r = 0; r < 4; r++) acc[mt][nt][r] = 0.0f;

    ISSUE(0, 0); CP_COMMIT();
    ISSUE(1, 1); CP_COMMIT();

    const int mL = lane >> 3, rL = lane & 7;
    const uint32_t offA = (uint32_t)(warp_m * 64 + (mL & 1) * 8 + rL) * RB + (mL >> 1) * 16;
    const uint32_t offB = (uint32_t)(warp_n * 32 + ((mL >= 2) ? 8 : 0) + rL) * RB + (mL & 1) * 16;

    const int lq = lane >> 2;
    const int lr = lane & 3;

    for (int kc = 0; kc < 16; kc++) {
        CP_WAIT1();
        __syncthreads();
        if (kc + 2 < 16) { ISSUE(kc + 2, (kc + 2) % 3); CP_COMMIT(); }

        const uint32_t stA = sb + (uint32_t)(kc % 3) * STAGE_B;
        const uint32_t stB = stA + ATILE_B;

#pragma unroll
        for (int ks = 0; ks < 4; ks++) {
            uint32_t af[4][4];
#pragma unroll
            for (int mt = 0; mt < 4; mt++)
                ldsm_x4(af[mt], stA + offA + mt * (16 * RB) + ks * 32);
            uint32_t b4[2][4];
#pragma unroll
            for (int ntp = 0; ntp < 2; ntp++)
                ldsm_x4(b4[ntp], stB + offB + ntp * (16 * RB) + ks * 32);
#pragma unroll
            for (int mt = 0; mt < 4; mt++)
#pragma unroll
                for (int nt = 0; nt < 4; nt++)
                    mma_f16(acc[mt][nt], af[mt], &b4[nt >> 1][(nt & 1) * 2]);
        }
    }

#pragma unroll
    for (int mt = 0; mt < 4; mt++) {
        int row = bm + warp_m * 64 + mt * 16 + lq;
#pragma unroll
        for (int nt = 0; nt < 4; nt++) {
            int col = bn + warp_n * 32 + nt * 8 + lr * 2;
            if (half_out) {
                uint32_t* Ch = (uint32_t*)C;
                Ch[((size_t)row * GN + col) >> 1] =
                    f16x2(acc[mt][nt][0] * sc, acc[mt][nt][1] * sc);
                Ch[((size_t)(row + 8) * GN + col) >> 1] =
                    f16x2(acc[mt][nt][2] * sc, acc[mt][nt][3] * sc);
            } else {
                float* Cf = (float*)C;
                *(float2*)&Cf[(size_t)row * GN + col]       = make_float2(acc[mt][nt][0], acc[mt][nt][1]);
                *(float2*)&Cf[(size_t)(row + 8) * GN + col] = make_float2(acc[mt][nt][2], acc[mt][nt][3]);
            }
        }
    }
#undef ISSUE
}

// ===========================================================================
// Flash attention fp16 v6: 64 q-rows/CTA, 4 warps x 16 rows, private P,
// scores pre-scaled in Q (no FMUL), denominators via ones-MMA (no FADD
// chain, no epilogue shuffles). 4 CTAs/SM.
// ===========================================================================
#define AST_KS 0
#define AST_VS (64 * RB)                          // 9216
#define AST_MW (2 * 64 * RB)                      // 18432
#define AST_BYTES (AST_MW + 1024)                 // 19456
#define PPRIV (2 * AST_BYTES)                     // 38912: per-warp P (4x16 rows)
#define ATTN_SMEM (PPRIV + 64 * RB)               // 48128
#define LW (L_ / 32)

__global__ __launch_bounds__(128, 4) void attn_tc(
    const __half* __restrict__ Q, const __half* __restrict__ Kg,
    const __half* __restrict__ V, const unsigned* __restrict__ mp,
    __half* __restrict__ ctx)
{
    extern __shared__ char smem[];
    uint32_t sb = smem_u32(smem);

    const int tid  = threadIdx.x;
    const int lane = tid & 31;
    const int wid  = tid >> 5;
    const int lq = lane >> 2;
    const int lr = lane & 3;
    const int bh = blockIdx.y;
    const int b  = bh >> 4;
    const int h  = bh & 15;
    const int q0 = blockIdx.x * 64;

    const size_t head_off = (size_t)h * HD_;

    const int mL = lane >> 3, rL = lane & 7;
    const uint32_t offP = PPRIV + (uint32_t)wid * (16 * RB)
                        + (uint32_t)((mL & 1) * 8 + rL) * RB + (mL >> 1) * 16;
    const uint32_t offK = (uint32_t)(((mL >= 2) ? 8 : 0) + rL) * RB + (mL & 1) * 16;
    const uint32_t offV = (uint32_t)rL * RB + (uint32_t)mL * 16;

    const int ra = wid * 16 + lq;
    const int rb = ra + 8;

#define AISSUE(t, st) do {                                                     \
        uint32_t base = sb + (uint32_t)(st) * AST_BYTES;                       \
        int k0_ = (t) * 64;                                                    \
        _Pragma("unroll")                                                      \
        for (int _i = 0; _i < 4; _i++) {                                       \
            int idx = tid + _i * 128;                                          \
            int r  = idx >> 3;                                                 \
            int ch = (idx & 7) << 4;                                           \
            const char* gk = (const char*)Kg + ((size_t)(b * L_ + k0_ + r) * D_ + head_off) * 2 + ch; \
            const char* gv = (const char*)V  + ((size_t)(b * L_ + k0_ + r) * D_ + head_off) * 2 + ch; \
            CP_ASYNC16(base + AST_KS + r * RB + ch, gk);                       \
            CP_ASYNC16(base + AST_VS + r * RB + ch, gv);                       \
        }                                                                      \
        if (tid < 64) {                                                        \
            const char* gm = (const char*)(mp + (size_t)(b * L_ + q0 + tid) * LW + ((t) << 1)); \
            CP_ASYNC8(base + AST_MW + tid * 8, gm);                            \
        }                                                                      \
    } while (0)

    // ---- stage Q into the private-P region ----
    {
        uint32_t qdst = sb + PPRIV;
#pragma unroll
        for (int _i = 0; _i < 4; _i++) {
            int idx = tid + _i * 128;
            int r  = idx >> 3;
            int ch = (idx & 7) << 4;
            const char* gq = (const char*)Q + ((size_t)(b * L_ + q0 + r) * D_ + head_off) * 2 + ch;
            CP_ASYNC16(qdst + r * RB + ch, gq);
        }
    }
    AISSUE(0, 0);
    CP_COMMIT();
    CP_WAIT0();
    __syncthreads();

    uint32_t qa[4][4];
#pragma unroll
    for (int s = 0; s < 4; s++)
        ldsm_x4(qa[s], sb + offP + s * 32);

    float oacc[8][4];
#pragma unroll
    for (int nt = 0; nt < 8; nt++)
#pragma unroll
        for (int e = 0; e < 4; e++) oacc[nt][e] = 0.0f;

    float lacc[4] = {0.0f, 0.0f, 0.0f, 0.0f};
    const uint32_t onesb[2] = {0x3C003C00u, 0x3C003C00u};   // fp16 {1,1}

    for (int t = 0; t < 32; t++) {
        if (t > 0) { CP_WAIT0(); __syncthreads(); }
        if (t + 1 < 32) { AISSUE(t + 1, (t + 1) & 1); CP_COMMIT(); }

        const uint32_t stg  = sb + (uint32_t)(t & 1) * AST_BYTES;
        const uint32_t stgV = stg + AST_VS;
        const unsigned* Mw = (const unsigned*)(smem + (t & 1) * AST_BYTES + AST_MW);

        // ---- S = Q K^T (Q pre-scaled by 1/8) ----
        float sacc[8][4];
#pragma unroll
        for (int nt = 0; nt < 8; nt++)
#pragma unroll
            for (int e = 0; e < 4; e++) sacc[nt][e] = 0.0f;

#pragma unroll
        for (int s = 0; s < 4; s++) {
            uint32_t kb4[4][4];
#pragma unroll
            for (int ntp = 0; ntp < 4; ntp++)
                ldsm_x4(kb4[ntp], stg + offK + ntp * (16 * RB) + s * 32);
#pragma unroll
            for (int nt = 0; nt < 8; nt++)
                mma_f16(sacc[nt], qa[s], &kb4[nt >> 1][(nt & 1) * 2]);
        }

        // ---- mask + exp + store P into this warp's private region ----
        const unsigned w0a = Mw[ra * 2], w0b = Mw[ra * 2 + 1];
        const unsigned w1a = Mw[rb * 2], w1b = Mw[rb * 2 + 1];
        char* Pc = (char*)smem + PPRIV + wid * (16 * RB);
#pragma unroll
        for (int nt = 0; nt < 8; nt++) {
            const int c = nt * 8 + 2 * lr;
            const int sh = c & 31;
            const unsigned wA = (nt < 4) ? w0a : w0b;
            const unsigned wB = (nt < 4) ? w1a : w1b;
            float t0 = ((wA >> sh) & 1u)       ? -1e9f : sacc[nt][0];
            float t1 = ((wA >> (sh + 1)) & 1u) ? -1e9f : sacc[nt][1];
            float t2 = ((wB >> sh) & 1u)       ? -1e9f : sacc[nt][2];
            float t3 = ((wB >> (sh + 1)) & 1u) ? -1e9f : sacc[nt][3];
            *(uint32_t*)(Pc + lq * RB + c * 2)       = f16x2(__expf(t0), __expf(t1));
            *(uint32_t*)(Pc + (lq + 8) * RB + c * 2) = f16x2(__expf(t2), __expf(t3));
        }
        __syncwarp();

        // ---- O += P V ; l += P * ones ----
#pragma unroll
        for (int s = 0; s < 4; s++) {
            uint32_t vA[4], vB[4], vC[4], vD[4];
            ldsm_x4_t(vA, stgV + offV + (s * 16 + 0) * RB + 0);
            ldsm_x4_t(vB, stgV + offV + (s * 16 + 8) * RB + 0);
            ldsm_x4_t(vC, stgV + offV + (s * 16 + 0) * RB + 64);
            ldsm_x4_t(vD, stgV + offV + (s * 16 + 8) * RB + 64);
            uint32_t pa[4];
            ldsm_x4(pa, sb + offP + s * 32);
            mma_f16(lacc, pa, onesb);
            uint32_t vb[8][2];
#pragma unroll
            for (int o = 0; o < 4; o++) {
                vb[o][0] = vA[o];     vb[o][1] = vB[o];
                vb[o + 4][0] = vC[o]; vb[o + 4][1] = vD[o];
            }
#pragma unroll
            for (int nt = 0; nt < 8; nt++)
                mma_f16(oacc[nt], pa, vb[nt]);
        }
        __syncwarp();
    }

    // ---- epilogue: l comes straight from ones-MMA accumulators ----
    float inv0 = 1.0f / lacc[0], inv1 = 1.0f / lacc[2];
    uint32_t* ctxu = (uint32_t*)ctx;
#pragma unroll
    for (int nt = 0; nt < 8; nt++) {
        int col = nt * 8 + 2 * lr;
        ctxu[(((size_t)(b * L_ + q0 + ra)) * D_ + head_off + col) >> 1] =
            f16x2(oacc[nt][0] * inv0, oacc[nt][1] * inv0);
        ctxu[(((size_t)(b * L_ + q0 + rb)) * D_ + head_off + col) >> 1] =
            f16x2(oacc[nt][2] * inv1, oacc[nt][3] * inv1);
    }
#undef AISSUE
}

// ---------------------------------------------------------------------------
extern "C" void kernel_launch(void* const* d_in, const int* in_sizes, int n_in,
                              void* d_out, int out_size)
{
    const float* q_in = (const float*)d_in[0];
    const float* k_in = (const float*)d_in[1];
    const float* v_in = (const float*)d_in[2];
    const float* Wq   = (const float*)d_in[3];
    const float* Wk   = (const float*)d_in[4];
    const float* Wv   = (const float*)d_in[5];
    const float* Wo   = (const float*)d_in[6];
    const int*   mask = (const int*)d_in[7];
    float* out = (float*)d_out;

    __half *pq, *pk, *pv, *pctx, *px0, *px1, *px2, *pw0, *pw1, *pw2, *pw3;
    unsigned* pm;
    cudaGetSymbolAddress((void**)&pq,   g_q);
    cudaGetSymbolAddress((void**)&pk,   g_k);
    cudaGetSymbolAddress((void**)&pv,   g_v);
    cudaGetSymbolAddress((void**)&pctx, g_ctx);
    cudaGetSymbolAddress((void**)&px0,  g_x0);
    cudaGetSymbolAddress((void**)&px1,  g_x1);
    cudaGetSymbolAddress((void**)&px2,  g_x2);
    cudaGetSymbolAddress((void**)&pw0,  g_w0);
    cudaGetSymbolAddress((void**)&pw1,  g_w1);
    cudaGetSymbolAddress((void**)&pw2,  g_w2);
    cudaGetSymbolAddress((void**)&pw3,  g_w3);
    cudaGetSymbolAddress((void**)&pm,   g_mpack);

    cudaFuncSetAttribute(gemm_tc, cudaFuncAttributeMaxDynamicSharedMemorySize, GEMM_SMEM);
    cudaFuncSetAttribute(attn_tc, cudaFuncAttributeMaxDynamicSharedMemorySize, ATTN_SMEM);

    // #0: mask pack
    mask_pack_kernel<<<(B_ * L_ * L_) / 1024, 256>>>(mask, pm);

    // #1: all fp32->fp16 rounding in one launch (z = 7 slices)
    round_half_all<<<dim3(M_ROWS * D_ / 2048, 7), 256>>>(
        q_in, k_in, v_in, Wq, Wk, Wv, Wo,
        px0, px1, px2, pw0, pw1, pw2, pw3);

    // #2: fused QKV projections; Q output pre-scaled by 1/8 (exact pow2)
    gemm_tc<<<dim3(GN / 128, M_ROWS / 128, 3), 256, GEMM_SMEM>>>(
        px0, px1, px2, pw0, pw1, pw2, pq, pk, pv, 1, 0.125f);

    // #3: attention (now in the ncu capture window)
    attn_tc<<<dim3(L_ / 64, B_ * H_), 128, ATTN_SMEM>>>(pq, pk, pv, pm, pctx);

    // #4: output projection (fp32 out)
    gemm_tc<<<dim3(GN / 128, M_ROWS / 128, 1), 256, GEMM_SMEM>>>(
        pctx, pctx, pctx, pw3, pw3, pw3, out, out, out, 0, 1.0f);
}

// round 17
// speedup vs baseline: 1.1083x; 1.0397x over previous
#include <cuda_runtime.h>
#include <cuda_fp16.h>
#include <math.h>
#include <stdint.h>

// Problem constants
#define B_ 2
#define L_ 2048
#define D_ 1024
#define H_ 16
#define HD_ 64
#define M_ROWS (B_ * L_)   // 4096
#define GK 1024
#define GN 1024

// Scratch (allocation-free rule: __device__ globals) — all half
__device__ __half g_q[M_ROWS * D_];
__device__ __half g_k[M_ROWS * D_];
__device__ __half g_v[M_ROWS * D_];
__device__ __half g_ctx[M_ROWS * D_];
__device__ __half g_x0[M_ROWS * D_];
__device__ __half g_x1[M_ROWS * D_];
__device__ __half g_x2[M_ROWS * D_];
__device__ __half g_w0[D_ * D_];
__device__ __half g_w1[D_ * D_];
__device__ __half g_w2[D_ * D_];
__device__ __half g_w3[D_ * D_];
__device__ unsigned g_mpack[B_ * L_ * (L_ / 32)];

// ===========================================================================
// Helpers
// ===========================================================================
__device__ __forceinline__ uint32_t smem_u32(const void* p) {
    uint32_t a;
    asm("{ .reg .u64 t; cvta.to.shared.u64 t, %1; cvt.u32.u64 %0, t; }" : "=r"(a) : "l"(p));
    return a;
}
#define CP_ASYNC16(s, g) \
    asm volatile("cp.async.cg.shared.global [%0], [%1], 16;" :: "r"(s), "l"(g))
#define CP_ASYNC8(s, g) \
    asm volatile("cp.async.ca.shared.global [%0], [%1], 8;" :: "r"(s), "l"(g))
#define CP_COMMIT() asm volatile("cp.async.commit_group;" ::: "memory")
#define CP_WAIT0()  asm volatile("cp.async.wait_group 0;" ::: "memory")
#define CP_WAIT1()  asm volatile("cp.async.wait_group 1;" ::: "memory")

// pack two f32 -> f16x2 (round-to-nearest)
__device__ __forceinline__ uint32_t f16x2(float lo, float hi) {
    uint32_t r;
    asm("cvt.rn.f16x2.f32 %0, %1, %2;" : "=r"(r) : "f"(hi), "f"(lo));
    return r;
}

// mma.sync fp16: D(16x8) += A(16x16) * B(16x8), fp32 accum
__device__ __forceinline__ void mma_f16(float* d, const uint32_t* a, const uint32_t* b) {
    asm volatile(
        "mma.sync.aligned.m16n8k16.row.col.f32.f16.f16.f32 "
        "{%0,%1,%2,%3}, {%4,%5,%6,%7}, {%8,%9}, {%0,%1,%2,%3};"
        : "+f"(d[0]), "+f"(d[1]), "+f"(d[2]), "+f"(d[3])
        : "r"(a[0]), "r"(a[1]), "r"(a[2]), "r"(a[3]), "r"(b[0]), "r"(b[1]));
}

__device__ __forceinline__ void ldsm_x4(uint32_t* r, uint32_t addr) {
    asm volatile("ldmatrix.sync.aligned.m8n8.x4.shared.b16 {%0,%1,%2,%3}, [%4];"
        : "=r"(r[0]), "=r"(r[1]), "=r"(r[2]), "=r"(r[3]) : "r"(addr));
}
__device__ __forceinline__ void ldsm_x4_t(uint32_t* r, uint32_t addr) {
    asm volatile("ldmatrix.sync.aligned.m8n8.x4.trans.shared.b16 {%0,%1,%2,%3}, [%4];"
        : "=r"(r[0]), "=r"(r[1]), "=r"(r[2]), "=r"(r[3]) : "r"(addr));
}

// ===========================================================================
// fp32 -> fp16 rounding pass, ALL 7 arrays in one launch (grid.y = 7)
// ===========================================================================
__global__ __launch_bounds__(256) void round_half_all(
    const float* __restrict__ i0, const float* __restrict__ i1,
    const float* __restrict__ i2, const float* __restrict__ i3,
    const float* __restrict__ i4, const float* __restrict__ i5,
    const float* __restrict__ i6,
    __half* __restrict__ o0, __half* __restrict__ o1,
    __half* __restrict__ o2, __half* __restrict__ o3,
    __half* __restrict__ o4, __half* __restrict__ o5,
    __half* __restrict__ o6)
{
    const int z = blockIdx.y;
    if (z >= 3 && blockIdx.x >= (D_ * D_) / 2048) return;
    const float* in;
    __half* out;
    switch (z) {
        case 0: in = i0; out = o0; break;
        case 1: in = i1; out = o1; break;
        case 2: in = i2; out = o2; break;
        case 3: in = i3; out = o3; break;
        case 4: in = i4; out = o4; break;
        case 5: in = i5; out = o5; break;
        default: in = i6; out = o6; break;
    }
    int idx = blockIdx.x * 256 + threadIdx.x;
    float4 a = ((const float4*)in)[idx * 2];
    float4 b = ((const float4*)in)[idx * 2 + 1];
    uint4 o;
    o.x = f16x2(a.x, a.y);
    o.y = f16x2(a.z, a.w);
    o.z = f16x2(b.x, b.y);
    o.w = f16x2(b.z, b.w);
    ((uint4*)out)[idx] = o;
}

// ===========================================================================
// Mask bit-pack: each warp packs 128 ints via 4 ballots; block = 1024 ints
// ===========================================================================
__global__ __launch_bounds__(256) void mask_pack_kernel(
    const int* __restrict__ m, unsigned* __restrict__ out)
{
    int warp = blockIdx.x * 8 + (threadIdx.x >> 5);
    int lane = threadIdx.x & 31;
    size_t base = (size_t)warp * 128;
    int v0 = m[base + lane], v1 = m[base + 32 + lane];
    int v2 = m[base + 64 + lane], v3 = m[base + 96 + lane];
    unsigned w0 = __ballot_sync(0xFFFFFFFFu, v0 != 0);
    unsigned w1 = __ballot_sync(0xFFFFFFFFu, v1 != 0);
    unsigned w2 = __ballot_sync(0xFFFFFFFFu, v2 != 0);
    unsigned w3 = __ballot_sync(0xFFFFFFFFu, v3 != 0);
    if (lane == 0) {
        out[warp * 4 + 0] = w0; out[warp * 4 + 1] = w1;
        out[warp * 4 + 2] = w2; out[warp * 4 + 3] = w3;
    }
}

// ===========================================================================
// fp16 mma.sync NT GEMM (2 CTAs/SM, reg cap 128); qscale folds 1/sqrt(HD)
// into the Q projection output.
// ===========================================================================
#define RB 144                           // bytes per smem row (64 halves + pad)
#define ATILE_B (128 * RB)               // 18432
#define STAGE_B (2 * ATILE_B)            // 36864
#define GEMM_SMEM (3 * STAGE_B)          // 110592

__global__ __launch_bounds__(256, 2) void gemm_tc(
    const __half* __restrict__ A0, const __half* __restrict__ A1, const __half* __restrict__ A2,
    const __half* __restrict__ B0, const __half* __restrict__ B1, const __half* __restrict__ B2,
    void* __restrict__ C0, void* __restrict__ C1, void* __restrict__ C2,
    int half_out, float qscale)
{
    extern __shared__ char smem[];
    uint32_t sb = smem_u32(smem);
    const int tid  = threadIdx.x;
    const int lane = tid & 31;
    const int wid  = tid >> 5;
    const int warp_m = wid & 1;
    const int warp_n = wid >> 1;
    const int bm = blockIdx.y * 128;
    const int bn = blockIdx.x * 128;
    const int z  = blockIdx.z;

    const __half* A = (z == 0) ? A0 : (z == 1) ? A1 : A2;
    const __half* Bw = (z == 0) ? B0 : (z == 1) ? B1 : B2;
    void* C = (z == 0) ? C0 : (z == 1) ? C1 : C2;
    const float sc = (half_out && z == 0) ? qscale : 1.0f;

    const char* Ab = (const char*)(A + (size_t)bm * GK);
    const char* Bb = (const char*)(Bw + (size_t)bn * GK);

#define ISSUE(kc, st) do {                                                    \
        uint32_t sA = sb + (uint32_t)(st) * STAGE_B;                          \
        uint32_t sB = sA + ATILE_B;                                           \
        size_t koff = (size_t)(kc) * 128;                                     \
        _Pragma("unroll")                                                     \
        for (int _i = 0; _i < 4; _i++) {                                      \
            int idx = tid + _i * 256;                                         \
            int r  = idx >> 3;                                                \
            int ch = (idx & 7) << 4;                                          \
            CP_ASYNC16(sA + r * RB + ch, Ab + (size_t)r * 2048 + koff + ch);  \
            CP_ASYNC16(sB + r * RB + ch, Bb + (size_t)r * 2048 + koff + ch);  \
        }                                                                     \
    } while (0)

    float acc[4][4][4];
#pragma unroll
    for (int mt = 0; mt < 4; mt++)
#pragma unroll
        for (int nt = 0; nt < 4; nt++)
#pragma unroll
            for (int r = 0; r < 4; r++) acc[mt][nt][r] = 0.0f;

    ISSUE(0, 0); CP_COMMIT();
    ISSUE(1, 1); CP_COMMIT();

    const int mL = lane >> 3, rL = lane & 7;
    const uint32_t offA = (uint32_t)(warp_m * 64 + (mL & 1) * 8 + rL) * RB + (mL >> 1) * 16;
    const uint32_t offB = (uint32_t)(warp_n * 32 + ((mL >= 2) ? 8 : 0) + rL) * RB + (mL & 1) * 16;

    const int lq = lane >> 2;
    const int lr = lane & 3;

    for (int kc = 0; kc < 16; kc++) {
        CP_WAIT1();
        __syncthreads();
        if (kc + 2 < 16) { ISSUE(kc + 2, (kc + 2) % 3); CP_COMMIT(); }

        const uint32_t stA = sb + (uint32_t)(kc % 3) * STAGE_B;
        const uint32_t stB = stA + ATILE_B;

#pragma unroll
        for (int ks = 0; ks < 4; ks++) {
            uint32_t af[4][4];
#pragma unroll
            for (int mt = 0; mt < 4; mt++)
                ldsm_x4(af[mt], stA + offA + mt * (16 * RB) + ks * 32);
            uint32_t b4[2][4];
#pragma unroll
            for (int ntp = 0; ntp < 2; ntp++)
                ldsm_x4(b4[ntp], stB + offB + ntp * (16 * RB) + ks * 32);
#pragma unroll
            for (int mt = 0; mt < 4; mt++)
#pragma unroll
                for (int nt = 0; nt < 4; nt++)
                    mma_f16(acc[mt][nt], af[mt], &b4[nt >> 1][(nt & 1) * 2]);
        }
    }

#pragma unroll
    for (int mt = 0; mt < 4; mt++) {
        int row = bm + warp_m * 64 + mt * 16 + lq;
#pragma unroll
        for (int nt = 0; nt < 4; nt++) {
            int col = bn + warp_n * 32 + nt * 8 + lr * 2;
            if (half_out) {
                uint32_t* Ch = (uint32_t*)C;
                Ch[((size_t)row * GN + col) >> 1] =
                    f16x2(acc[mt][nt][0] * sc, acc[mt][nt][1] * sc);
                Ch[((size_t)(row + 8) * GN + col) >> 1] =
                    f16x2(acc[mt][nt][2] * sc, acc[mt][nt][3] * sc);
            } else {
                float* Cf = (float*)C;
                *(float2*)&Cf[(size_t)row * GN + col]       = make_float2(acc[mt][nt][0], acc[mt][nt][1]);
                *(float2*)&Cf[(size_t)(row + 8) * GN + col] = make_float2(acc[mt][nt][2], acc[mt][nt][3]);
            }
        }
    }
#undef ISSUE
}

// ===========================================================================
// Flash attention fp16 v7: 64 q-rows/CTA, 4 warps x 16 rows.
// P NEVER touches smem: S accumulators are masked, exponentiated, and packed
// (f16x2) directly into PV A-fragments (register repack — layouts coincide).
// Denominators via ones-MMA. Fixed-max softmax. 4 CTAs/SM.
// ===========================================================================
#define AST_KS 0
#define AST_VS (64 * RB)                          // 9216
#define AST_MW (2 * 64 * RB)                      // 18432
#define AST_BYTES (AST_MW + 1024)                 // 19456
#define QOFF (2 * AST_BYTES)                      // 38912: Q staging (64 rows)
#define ATTN_SMEM (QOFF + 64 * RB)                // 48128
#define LW (L_ / 32)

__global__ __launch_bounds__(128, 4) void attn_tc(
    const __half* __restrict__ Q, const __half* __restrict__ Kg,
    const __half* __restrict__ V, const unsigned* __restrict__ mp,
    __half* __restrict__ ctx)
{
    extern __shared__ char smem[];
    uint32_t sb = smem_u32(smem);

    const int tid  = threadIdx.x;
    const int lane = tid & 31;
    const int wid  = tid >> 5;
    const int lq = lane >> 2;
    const int lr = lane & 3;
    const int bh = blockIdx.y;
    const int b  = bh >> 4;
    const int h  = bh & 15;
    const int q0 = blockIdx.x * 64;

    const size_t head_off = (size_t)h * HD_;

    const int mL = lane >> 3, rL = lane & 7;
    const uint32_t offQ = QOFF + (uint32_t)(wid * 16 + (mL & 1) * 8 + rL) * RB + (mL >> 1) * 16;
    const uint32_t offK = (uint32_t)(((mL >= 2) ? 8 : 0) + rL) * RB + (mL & 1) * 16;
    const uint32_t offV = (uint32_t)rL * RB + (uint32_t)mL * 16;

    const int ra = wid * 16 + lq;
    const int rb = ra + 8;

#define AISSUE(t, st) do {                                                     \
        uint32_t base = sb + (uint32_t)(st) * AST_BYTES;                       \
        int k0_ = (t) * 64;                                                    \
        _Pragma("unroll")                                                      \
        for (int _i = 0; _i < 4; _i++) {                                       \
            int idx = tid + _i * 128;                                          \
            int r  = idx >> 3;                                                 \
            int ch = (idx & 7) << 4;                                           \
            const char* gk = (const char*)Kg + ((size_t)(b * L_ + k0_ + r) * D_ + head_off) * 2 + ch; \
            const char* gv = (const char*)V  + ((size_t)(b * L_ + k0_ + r) * D_ + head_off) * 2 + ch; \
            CP_ASYNC16(base + AST_KS + r * RB + ch, gk);                       \
            CP_ASYNC16(base + AST_VS + r * RB + ch, gv);                       \
        }                                                                      \
        if (tid < 64) {                                                        \
            const char* gm = (const char*)(mp + (size_t)(b * L_ + q0 + tid) * LW + ((t) << 1)); \
            CP_ASYNC8(base + AST_MW + tid * 8, gm);                            \
        }                                                                      \
    } while (0)

    // ---- stage Q into its dedicated region ----
    {
        uint32_t qdst = sb + QOFF;
#pragma unroll
        for (int _i = 0; _i < 4; _i++) {
            int idx = tid + _i * 128;
            int r  = idx >> 3;
            int ch = (idx & 7) << 4;
            const char* gq = (const char*)Q + ((size_t)(b * L_ + q0 + r) * D_ + head_off) * 2 + ch;
            CP_ASYNC16(qdst + r * RB + ch, gq);
        }
    }
    AISSUE(0, 0);
    CP_COMMIT();
    CP_WAIT0();
    __syncthreads();

    uint32_t qa[4][4];
#pragma unroll
    for (int s = 0; s < 4; s++)
        ldsm_x4(qa[s], sb + offQ + s * 32);
    // Q region is never overwritten; no barrier needed here.

    float oacc[8][4];
#pragma unroll
    for (int nt = 0; nt < 8; nt++)
#pragma unroll
        for (int e = 0; e < 4; e++) oacc[nt][e] = 0.0f;

    float lacc[4] = {0.0f, 0.0f, 0.0f, 0.0f};
    const uint32_t onesb[2] = {0x3C003C00u, 0x3C003C00u};   // fp16 {1,1}

    for (int t = 0; t < 32; t++) {
        if (t > 0) { CP_WAIT0(); __syncthreads(); }
        if (t + 1 < 32) { AISSUE(t + 1, (t + 1) & 1); CP_COMMIT(); }

        const uint32_t stg  = sb + (uint32_t)(t & 1) * AST_BYTES;
        const uint32_t stgV = stg + AST_VS;
        const unsigned* Mw = (const unsigned*)(smem + (t & 1) * AST_BYTES + AST_MW);

        // ---- S = Q K^T (Q pre-scaled by 1/8) ----
        float sacc[8][4];
#pragma unroll
        for (int nt = 0; nt < 8; nt++)
#pragma unroll
            for (int e = 0; e < 4; e++) sacc[nt][e] = 0.0f;

#pragma unroll
        for (int s = 0; s < 4; s++) {
            uint32_t kb4[4][4];
#pragma unroll
            for (int ntp = 0; ntp < 4; ntp++)
                ldsm_x4(kb4[ntp], stg + offK + ntp * (16 * RB) + s * 32);
#pragma unroll
            for (int nt = 0; nt < 8; nt++)
                mma_f16(sacc[nt], qa[s], &kb4[nt >> 1][(nt & 1) * 2]);
        }

        // ---- mask + exp + pack DIRECTLY into PV A-fragments (no smem) ----
        const unsigned w0a = Mw[ra * 2], w0b = Mw[ra * 2 + 1];
        const unsigned w1a = Mw[rb * 2], w1b = Mw[rb * 2 + 1];
        uint32_t pa[4][4];
#pragma unroll
        for (int nt = 0; nt < 8; nt++) {
            const int c = nt * 8 + 2 * lr;
            const int sh = c & 31;
            const unsigned wA = (nt < 4) ? w0a : w0b;
            const unsigned wB = (nt < 4) ? w1a : w1b;
            float t0 = ((wA >> sh) & 1u)       ? -1e9f : sacc[nt][0];
            float t1 = ((wA >> (sh + 1)) & 1u) ? -1e9f : sacc[nt][1];
            float t2 = ((wB >> sh) & 1u)       ? -1e9f : sacc[nt][2];
            float t3 = ((wB >> (sh + 1)) & 1u) ? -1e9f : sacc[nt][3];
            // S acc layout == PV A-frag layout:
            // pa[s] = { (row lq, k lo-octet), (row lq+8, k lo-octet),
            //           (row lq, k hi-octet), (row lq+8, k hi-octet) }
            pa[nt >> 1][(nt & 1) * 2 + 0] = f16x2(__expf(t0), __expf(t1));
            pa[nt >> 1][(nt & 1) * 2 + 1] = f16x2(__expf(t2), __expf(t3));
        }

        // ---- O += P V ; l += P * ones ----
#pragma unroll
        for (int s = 0; s < 4; s++) {
            uint32_t vA[4], vB[4], vC[4], vD[4];
            ldsm_x4_t(vA, stgV + offV + (s * 16 + 0) * RB + 0);
            ldsm_x4_t(vB, stgV + offV + (s * 16 + 8) * RB + 0);
            ldsm_x4_t(vC, stgV + offV + (s * 16 + 0) * RB + 64);
            ldsm_x4_t(vD, stgV + offV + (s * 16 + 8) * RB + 64);
            mma_f16(lacc, pa[s], onesb);
            uint32_t vb[8][2];
#pragma unroll
            for (int o = 0; o < 4; o++) {
                vb[o][0] = vA[o];     vb[o][1] = vB[o];
                vb[o + 4][0] = vC[o]; vb[o + 4][1] = vD[o];
            }
#pragma unroll
            for (int nt = 0; nt < 8; nt++)
                mma_f16(oacc[nt], pa[s], vb[nt]);
        }
    }

    // ---- epilogue: l from ones-MMA accumulators ----
    float inv0 = 1.0f / lacc[0], inv1 = 1.0f / lacc[2];
    uint32_t* ctxu = (uint32_t*)ctx;
#pragma unroll
    for (int nt = 0; nt < 8; nt++) {
        int col = nt * 8 + 2 * lr;
        ctxu[(((size_t)(b * L_ + q0 + ra)) * D_ + head_off + col) >> 1] =
            f16x2(oacc[nt][0] * inv0, oacc[nt][1] * inv0);
        ctxu[(((size_t)(b * L_ + q0 + rb)) * D_ + head_off + col) >> 1] =
            f16x2(oacc[nt][2] * inv1, oacc[nt][3] * inv1);
    }
#undef AISSUE
}

// ---------------------------------------------------------------------------
extern "C" void kernel_launch(void* const* d_in, const int* in_sizes, int n_in,
                              void* d_out, int out_size)
{
    const float* q_in = (const float*)d_in[0];
    const float* k_in = (const float*)d_in[1];
    const float* v_in = (const float*)d_in[2];
    const float* Wq   = (const float*)d_in[3];
    const float* Wk   = (const float*)d_in[4];
    const float* Wv   = (const float*)d_in[5];
    const float* Wo   = (const float*)d_in[6];
    const int*   mask = (const int*)d_in[7];
    float* out = (float*)d_out;

    __half *pq, *pk, *pv, *pctx, *px0, *px1, *px2, *pw0, *pw1, *pw2, *pw3;
    unsigned* pm;
    cudaGetSymbolAddress((void**)&pq,   g_q);
    cudaGetSymbolAddress((void**)&pk,   g_k);
    cudaGetSymbolAddress((void**)&pv,   g_v);
    cudaGetSymbolAddress((void**)&pctx, g_ctx);
    cudaGetSymbolAddress((void**)&px0,  g_x0);
    cudaGetSymbolAddress((void**)&px1,  g_x1);
    cudaGetSymbolAddress((void**)&px2,  g_x2);
    cudaGetSymbolAddress((void**)&pw0,  g_w0);
    cudaGetSymbolAddress((void**)&pw1,  g_w1);
    cudaGetSymbolAddress((void**)&pw2,  g_w2);
    cudaGetSymbolAddress((void**)&pw3,  g_w3);
    cudaGetSymbolAddress((void**)&pm,   g_mpack);

    cudaFuncSetAttribute(gemm_tc, cudaFuncAttributeMaxDynamicSharedMemorySize, GEMM_SMEM);
    cudaFuncSetAttribute(attn_tc, cudaFuncAttributeMaxDynamicSharedMemorySize, ATTN_SMEM);

    // #0: mask pack
    mask_pack_kernel<<<(B_ * L_ * L_) / 1024, 256>>>(mask, pm);

    // #1: all fp32->fp16 rounding in one launch
    round_half_all<<<dim3(M_ROWS * D_ / 2048, 7), 256>>>(
        q_in, k_in, v_in, Wq, Wk, Wv, Wo,
        px0, px1, px2, pw0, pw1, pw2, pw3);

    // #2: fused QKV projections; Q pre-scaled by 1/8
    gemm_tc<<<dim3(GN / 128, M_ROWS / 128, 3), 256, GEMM_SMEM>>>(
        px0, px1, px2, pw0, pw1, pw2, pq, pk, pv, 1, 0.125f);

    // #3: attention (in the ncu capture window)
    attn_tc<<<dim3(L_ / 64, B_ * H_), 128, ATTN_SMEM>>>(pq, pk, pv, pm, pctx);

    // #4: output projection (fp32 out)
    gemm_tc<<<dim3(GN / 128, M_ROWS / 128, 1), 256, GEMM_SMEM>>>(
        pctx, pctx, pctx, pw3, pw3, pw3, out, out, out, 0, 1.0f);
}